// round 11
// baseline (speedup 1.0000x reference)
#include <cuda_runtime.h>
#include <cuda_fp16.h>
#include <cstdint>

#define Hdim 256
#define Bdim 2048
#define Tdim 512
#define Vdim 64
#define NB   16          // batches per CTA -> 128 CTAs
#define NTH  512         // 16 warps: pair p = {warp p (K-low), warp p+8 (K-high)}
#define HSTR 264         // h row stride in halfs (528B)
#define PSTR 266         // P row stride in floats
#define ESTR 68          // embT row stride in floats
#define SCRSTR 17        // partial scratch per-lane stride in floats (odd -> conflict-free)

// ---- shared memory layout (bytes) ----
#define SM_P    0                      // P[64][PSTR] f32 = 68096
#define SM_H0   68096                  // h buf0: 16 x 264 halfs = 8448
#define SM_H1   76544                  // h buf1: 8448
#define SM_TOK  84992                  // tokens [512][16] int = 32768
#define SM_MBAR 117760                 // mbarrier
#define SM_SCR  117888                 // partial scratch: 8 pairs x 32 x 17 f32 = 17408
#define SM_EMBT 117888                 // transient embT f32 (prologue only, overlaps SCR)
#define SMEM_TOTAL (117888 + 69632)    // 187520

// ---------------------------------------------------------------------------
__device__ __forceinline__ uint32_t smem_u32(const void* p) {
    uint32_t a;
    asm("{ .reg .u64 t; cvta.to.shared.u64 t, %1; cvt.u32.u64 %0, t; }"
        : "=r"(a) : "l"(p));
    return a;
}
// sigmoid via single-MUFU tanh: s = 0.5*tanh(0.5x) + 0.5
__device__ __forceinline__ float sigmoid_t(float x) {
    float t;
    asm("tanh.approx.f32 %0, %1;" : "=f"(t) : "f"(0.5f * x));
    return fmaf(0.5f, t, 0.5f);
}
__device__ __forceinline__ void ffma2(unsigned long long& d,
                                      unsigned long long a, unsigned long long b) {
    asm("fma.rn.f32x2 %0, %1, %2, %0;" : "+l"(d) : "l"(a), "l"(b));
}
__device__ __forceinline__ unsigned long long pack2(float lo, float hi) {
    unsigned long long r;
    asm("mov.b64 %0, {%1, %2};" : "=l"(r) : "f"(lo), "f"(hi));
    return r;
}
__device__ __forceinline__ void mma16816(float* d, const uint32_t* a,
                                         uint32_t b0, uint32_t b1) {
    asm volatile(
        "mma.sync.aligned.m16n8k16.row.col.f32.f16.f16.f32 "
        "{%0,%1,%2,%3}, {%4,%5,%6,%7}, {%8,%9}, {%0,%1,%2,%3};"
        : "+f"(d[0]), "+f"(d[1]), "+f"(d[2]), "+f"(d[3])
        : "r"(a[0]), "r"(a[1]), "r"(a[2]), "r"(a[3]), "r"(b0), "r"(b1));
}
__device__ __forceinline__ void ldmx4(uint32_t& r0, uint32_t& r1,
                                      uint32_t& r2, uint32_t& r3, uint32_t addr) {
    asm volatile(
        "ldmatrix.sync.aligned.m8n8.x4.shared.b16 {%0,%1,%2,%3}, [%4];"
        : "=r"(r0), "=r"(r1), "=r"(r2), "=r"(r3) : "r"(addr));
}
#define MBAR_INIT(mb, c) asm volatile("mbarrier.init.shared.b64 [%0], %1;" \
                                      :: "r"(mb), "r"(c) : "memory")
#define MBAR_ARRIVE(mb)  asm volatile("mbarrier.arrive.shared.b64 _, [%0];" \
                                      :: "r"(mb) : "memory")
__device__ __forceinline__ void mbar_wait(uint32_t mb, uint32_t parity) {
    asm volatile(
        "{ .reg .pred P;\n\t"
        "W_%=:\n\t"
        "mbarrier.try_wait.parity.acquire.cta.shared::cta.b64 P, [%0], %1, 0x989680;\n\t"
        "@P bra.uni D_%=;\n\t"
        "bra.uni W_%=;\n\t"
        "D_%=: }"
        :: "r"(mb), "r"(parity) : "memory");
}
// 64-thread pair barrier (warps p and p+8), ids 1..8
__device__ __forceinline__ void bar_pair(int id) {
    asm volatile("bar.sync %0, 64;" :: "r"(id) : "memory");
}

// ---------------------------------------------------------------------------
// Persistent RNN, K-split warp pairs.
// Pair p owns outputs [32p, 32p+32) (4 n8 tiles). Warp p accumulates
// K[0:128) (P-init included); warp p+8 accumulates K[128:256) and writes its
// 16 partials to conflict-free scratch. bar.sync(p+1, 64) orders the
// handoff; warp p reduces, applies sigmoid, stores h' + output.
// Single CTA-wide mbarrier phases the recurrence (everyone arrives once).
// ---------------------------------------------------------------------------
__global__ __launch_bounds__(NTH, 1)
void k_rnn(const int* __restrict__ tokens,
           const float* __restrict__ h0,
           const float* __restrict__ emb,
           const float* __restrict__ W,
           const float* __restrict__ bias,
           float* __restrict__ out) {
    extern __shared__ char smem[];
    const uint32_t sbase = smem_u32(smem);
    float* Psm  = (float*)(smem + SM_P);
    int*   toks = (int*)(smem + SM_TOK);
    const uint32_t mbar = sbase + SM_MBAR;

    const int tid  = threadIdx.x;
    const int wid  = tid >> 5;
    const int lane = tid & 31;
    const int g    = lane >> 2;     // 0..7
    const int r    = lane & 3;      // 0..3
    const int pair = wid & 7;       // 0..7
    const int role = wid >> 3;      // 0 = K-low + reducer, 1 = K-high
    const int bbase = blockIdx.x * NB;

    // ============== Prologue ==============
    {
        float* embT = (float*)(smem + SM_EMBT);
        for (int idx = tid; idx < Vdim * Hdim; idx += NTH) {
            int v = idx >> 8, k = idx & 255;
            embT[(size_t)k * ESTR + v] = emb[(size_t)v * Hdim + k];
        }
    }
    __syncthreads();
    {   // P[v][o] = bias[o] + emb[v,:]·Wx[o,:]; thread: o = tid&255, 2 v-groups
        const float* embT = (const float*)(smem + SM_EMBT);
        const int o = tid & 255;
        const int vg0 = (tid >> 8) * 2;
        const float bo = bias[o];
        const float4* wrow = (const float4*)(W + (size_t)o * (2 * Hdim));
        for (int vg = vg0; vg < vg0 + 2; ++vg) {
            unsigned long long acc[8];
#pragma unroll
            for (int i = 0; i < 8; ++i) acc[i] = pack2(0.f, 0.f);
            for (int k4 = 0; k4 < Hdim / 4; ++k4) {
                float4 wv = wrow[k4];
#pragma unroll
                for (int kk = 0; kk < 4; ++kk) {
                    int k = k4 * 4 + kk;
                    float w = (kk == 0) ? wv.x : (kk == 1) ? wv.y : (kk == 2) ? wv.z : wv.w;
                    unsigned long long wpair = pack2(w, w);
                    const ulonglong2* ep =
                        (const ulonglong2*)(embT + (size_t)k * ESTR + vg * 16);
                    ulonglong2 e0 = ep[0], e1 = ep[1], e2 = ep[2], e3 = ep[3];
                    ffma2(acc[0], wpair, e0.x); ffma2(acc[1], wpair, e0.y);
                    ffma2(acc[2], wpair, e1.x); ffma2(acc[3], wpair, e1.y);
                    ffma2(acc[4], wpair, e2.x); ffma2(acc[5], wpair, e2.y);
                    ffma2(acc[6], wpair, e3.x); ffma2(acc[7], wpair, e3.y);
                }
            }
#pragma unroll
            for (int i = 0; i < 8; ++i) {
                float lo = __uint_as_float((uint32_t)(acc[i] & 0xffffffffu));
                float hi = __uint_as_float((uint32_t)(acc[i] >> 32));
                int v0 = vg * 16 + 2 * i;
                Psm[(size_t)v0 * PSTR + o]       = bo + lo;
                Psm[(size_t)(v0 + 1) * PSTR + o] = bo + hi;
            }
        }
    }
    // B fragments: pair owns outputs [32p, 32p+32) -> 4 n8 tiles; this warp
    // covers its K-half (8 chunks): global chunk = c + 8*role.
    uint32_t breg[4][8][2];
#pragma unroll
    for (int nt = 0; nt < 4; ++nt) {
        int n = pair * 32 + nt * 8 + g;
        const float* wr = W + (size_t)n * (2 * Hdim) + Hdim;
#pragma unroll
        for (int c = 0; c < 8; ++c) {
            int k0 = (c + 8 * role) * 16 + 2 * r;
            float2 lo = *(const float2*)&wr[k0];
            float2 hi = *(const float2*)&wr[k0 + 8];
            __half2 hlo = __floats2half2_rn(lo.x, lo.y);
            __half2 hhi = __floats2half2_rn(hi.x, hi.y);
            breg[nt][c][0] = *(uint32_t*)&hlo;
            breg[nt][c][1] = *(uint32_t*)&hhi;
        }
    }
    for (int idx = tid; idx < NB * Tdim; idx += NTH) {
        int b = idx >> 9, t = idx & 511;
        toks[t * NB + b] = tokens[(size_t)(bbase + b) * Tdim + t];
    }
    {
        __half* hb = (__half*)(smem + SM_H0);
        for (int idx = tid; idx < NB * Hdim; idx += NTH) {
            int b = idx >> 8, k = idx & 255;
            hb[(size_t)b * HSTR + k] =
                __float2half_rn(h0[(size_t)(bbase + b) * Hdim + k]);
        }
    }
    if (tid == 0) MBAR_INIT(mbar, NTH);
    __syncthreads();
    MBAR_ARRIVE(mbar);       // phase 0: h(0) published

    // ldmatrix lane address; chunk offset adds (c + 8*role)*32 bytes
    const uint32_t ldm_base =
        (uint32_t)((lane & 15) * (HSTR * 2) + (lane >> 4) * 16)
        + (uint32_t)(role * 8 * 32);
    const int o0 = pair * 32 + 2 * r;
    float* const outcta = out + (size_t)bbase * Hdim;
    float* const scr = (float*)(smem + SM_SCR) + (size_t)pair * (32 * SCRSTR)
                       + (size_t)lane * SCRSTR;

    // ============== Recurrent loop ==============
    for (int t = 0; t < Tdim; ++t) {
        float d[4][4];
        if (role == 0) {
            // P prefetch (stable region, before the wait)
            const int tk0 = toks[t * NB + g];
            const int tk1 = toks[t * NB + g + 8];
#pragma unroll
            for (int nt = 0; nt < 4; ++nt) {
                float2 p0 = *(const float2*)&Psm[(size_t)tk0 * PSTR + o0 + nt * 8];
                float2 p1 = *(const float2*)&Psm[(size_t)tk1 * PSTR + o0 + nt * 8];
                d[nt][0] = p0.x; d[nt][1] = p0.y;
                d[nt][2] = p1.x; d[nt][3] = p1.y;
            }
        } else {
#pragma unroll
            for (int nt = 0; nt < 4; ++nt)
#pragma unroll
                for (int j = 0; j < 4; ++j) d[nt][j] = 0.f;
        }

        mbar_wait(mbar, (uint32_t)(t & 1));
        const uint32_t abuf = sbase + ((t & 1) ? SM_H1 : SM_H0) + ldm_base;

        // this warp's K-half: 8 chunks x 4 n-tiles
#pragma unroll
        for (int c = 0; c < 8; ++c) {
            uint32_t a[4];
            ldmx4(a[0], a[1], a[2], a[3], abuf + (uint32_t)c * 32);
            mma16816(d[0], a, breg[0][c][0], breg[0][c][1]);
            mma16816(d[1], a, breg[1][c][0], breg[1][c][1]);
            mma16816(d[2], a, breg[2][c][0], breg[2][c][1]);
            mma16816(d[3], a, breg[3][c][0], breg[3][c][1]);
        }

        if (role == 1) {
            // publish partials (conflict-free stride-17), handshake, arrive
#pragma unroll
            for (int nt = 0; nt < 4; ++nt)
#pragma unroll
                for (int j = 0; j < 4; ++j) scr[nt * 4 + j] = d[nt][j];
            bar_pair(pair + 1);
            MBAR_ARRIVE(mbar);
        } else {
            bar_pair(pair + 1);
            // reduce + sigmoid + h' store, then arrive; STG in the shadow
            float s[4][4];
            __half* hn = (__half*)(smem + ((t & 1) ? SM_H0 : SM_H1));
#pragma unroll
            for (int nt = 0; nt < 4; ++nt) {
                s[nt][0] = sigmoid_t(d[nt][0] + scr[nt * 4 + 0]);
                s[nt][1] = sigmoid_t(d[nt][1] + scr[nt * 4 + 1]);
                s[nt][2] = sigmoid_t(d[nt][2] + scr[nt * 4 + 2]);
                s[nt][3] = sigmoid_t(d[nt][3] + scr[nt * 4 + 3]);
                int o = o0 + nt * 8;
                *(__half2*)&hn[(size_t)g * HSTR + o] =
                    __floats2half2_rn(s[nt][0], s[nt][1]);
                *(__half2*)&hn[(size_t)(g + 8) * HSTR + o] =
                    __floats2half2_rn(s[nt][2], s[nt][3]);
            }
            MBAR_ARRIVE(mbar);

            float* outp = outcta + (size_t)t * (Bdim * Hdim);
#pragma unroll
            for (int nt = 0; nt < 4; ++nt) {
                int o = o0 + nt * 8;
                *(float2*)&outp[(size_t)g * Hdim + o] =
                    make_float2(s[nt][0], s[nt][1]);
                *(float2*)&outp[(size_t)(g + 8) * Hdim + o] =
                    make_float2(s[nt][2], s[nt][3]);
            }
        }
    }
}

// ---------------------------------------------------------------------------
// Harness entry.
// Inputs: tokens(i32 2048x512), h0(f32 2048x256), emb(f32 64x256),
//         W(f32 256x512), b(f32 256).  Output: f32 (512,2048,256)
// ---------------------------------------------------------------------------
extern "C" void kernel_launch(void* const* d_in, const int* in_sizes, int n_in,
                              void* d_out, int out_size) {
    const int*   tokens = (const int*)d_in[0];
    const float* h0     = (const float*)d_in[1];
    const float* emb    = (const float*)d_in[2];
    const float* W      = (const float*)d_in[3];
    const float* bias   = (const float*)d_in[4];
    float*       out    = (float*)d_out;
    (void)in_sizes; (void)n_in; (void)out_size;

    cudaFuncSetAttribute(k_rnn, cudaFuncAttributeMaxDynamicSharedMemorySize, SMEM_TOTAL);
    k_rnn<<<Bdim / NB, NTH, SMEM_TOTAL>>>(tokens, h0, emb, W, bias, out);
}